// round 17
// baseline (speedup 1.0000x reference)
#include <cuda_runtime.h>
#include <cuda_fp16.h>
#include <math.h>
#include <stdint.h>

// ---------------------------------------------------------------------------
// Scratch (static device arrays; no allocation allowed).
// ---------------------------------------------------------------------------
__device__ __half g_x16[32u * 512u * 512u];    // x  as f16   [B][T][D]
__device__ __half g_h16[32u * 512u * 1024u];   // h  as f16   [B][T][MID]
__device__ __half g_w1h[64u * 512u * 1024u];   // w1 f16      [S][K=D][N=MID]
__device__ __half g_w2h[64u * 1024u * 512u];   // w2 f16      [S][K=MID][N=O]

// ---------------------------------------------------------------------------
// helpers
// ---------------------------------------------------------------------------
__device__ __forceinline__ uint32_t smem_u32(const void* p) {
    uint32_t a;
    asm("{ .reg .u64 t; cvta.to.shared.u64 t, %1; cvt.u32.u64 %0, t; }"
        : "=r"(a) : "l"(p));
    return a;
}

__device__ __forceinline__ void cp_async16(uint32_t saddr, const void* gptr) {
    asm volatile("cp.async.cg.shared.global [%0], [%1], 16;"
                 :: "r"(saddr), "l"(gptr) : "memory");
}
__device__ __forceinline__ void cp_commit() {
    asm volatile("cp.async.commit_group;" ::: "memory");
}
template <int N>
__device__ __forceinline__ void cp_wait() {
    asm volatile("cp.async.wait_group %0;" :: "n"(N) : "memory");
}

__device__ __forceinline__ void ldsm_x4(uint32_t r[4], uint32_t addr) {
    asm volatile("ldmatrix.sync.aligned.m8n8.x4.shared.b16 {%0,%1,%2,%3}, [%4];"
                 : "=r"(r[0]), "=r"(r[1]), "=r"(r[2]), "=r"(r[3])
                 : "r"(addr));
}
__device__ __forceinline__ void ldsm_x4_t(uint32_t r[4], uint32_t addr) {
    asm volatile("ldmatrix.sync.aligned.m8n8.x4.trans.shared.b16 {%0,%1,%2,%3}, [%4];"
                 : "=r"(r[0]), "=r"(r[1]), "=r"(r[2]), "=r"(r[3])
                 : "r"(addr));
}

__device__ __forceinline__ void mma_f16(float c[4], const uint32_t a[4],
                                        uint32_t b0, uint32_t b1) {
    asm volatile(
        "mma.sync.aligned.m16n8k16.row.col.f32.f16.f16.f32 "
        "{%0,%1,%2,%3}, {%4,%5,%6,%7}, {%8,%9}, {%0,%1,%2,%3};"
        : "+f"(c[0]), "+f"(c[1]), "+f"(c[2]), "+f"(c[3])
        : "r"(a[0]), "r"(a[1]), "r"(a[2]), "r"(a[3]), "r"(b0), "r"(b1));
}

// sid dtype sniff (int32 vs int64), proven in rounds 4-16.
__device__ __forceinline__ int load_sid(const int* __restrict__ raw, int b) {
    bool is64 = true;
    #pragma unroll
    for (int i = 0; i < 16; i++)
        if (raw[2 * i + 1] != 0) { is64 = false; break; }
    int s = is64 ? raw[2 * b] : raw[b];
    if (s < 0) s = 0;
    if (s > 63) s = 63;
    return s;
}

__device__ __forceinline__ bool subject_used(const int* __restrict__ raw, int s) {
    bool is64 = true;
    #pragma unroll
    for (int i = 0; i < 16; i++)
        if (raw[2 * i + 1] != 0) { is64 = false; break; }
    #pragma unroll
    for (int b = 0; b < 32; b++) {
        int v = is64 ? raw[2 * b] : raw[b];
        if (v == s) return true;
    }
    return false;
}

// ---------------------------------------------------------------------------
// Conversion kernels (pure streaming)
// ---------------------------------------------------------------------------
__global__ void convert_x_kernel(const float4* __restrict__ in,
                                 uint2* __restrict__ out, int n4) {
    for (int i = blockIdx.x * blockDim.x + threadIdx.x; i < n4;
         i += gridDim.x * blockDim.x) {
        float4 v = in[i];
        __half2 lo = __floats2half2_rn(v.x, v.y);
        __half2 hi = __floats2half2_rn(v.z, v.w);
        uint2 u;
        u.x = *reinterpret_cast<uint32_t*>(&lo);
        u.y = *reinterpret_cast<uint32_t*>(&hi);
        out[i] = u;
    }
}

// Both weight tensors in one launch: blockIdx.y selects (w1 | w2).
// w [S][K][N] f32 -> f16 same layout, used subjects only.
__global__ void convert_w_both_kernel(const float4* __restrict__ in1,
                                      uint2* __restrict__ out1,
                                      const float4* __restrict__ in2,
                                      uint2* __restrict__ out2,
                                      const int* __restrict__ sid_raw,
                                      int elems4_per_subject) {
    const int s = blockIdx.z;
    if (!subject_used(sid_raw, s)) return;
    const float4* ip = (blockIdx.y == 0 ? in1 : in2) + (size_t)s * elems4_per_subject;
    uint2* op = (blockIdx.y == 0 ? out1 : out2) + (size_t)s * elems4_per_subject;
    for (int i = blockIdx.x * blockDim.x + threadIdx.x; i < elems4_per_subject;
         i += gridDim.x * blockDim.x) {
        float4 v = ip[i];
        __half2 lo = __floats2half2_rn(v.x, v.y);
        __half2 hi = __floats2half2_rn(v.z, v.w);
        uint2 u;
        u.x = *reinterpret_cast<uint32_t*>(&lo);
        u.y = *reinterpret_cast<uint32_t*>(&hi);
        op[i] = u;
    }
}

// ---------------------------------------------------------------------------
// fp16 mma.sync GEMM. r16 base (CTA 128x128, 256 thr, 8 warps 4(m)x2(n),
// warp 32x64, NSTAGE=4, mainloop unrolled by NSTAGE) + B-fragment register
// prefetch with COMPILE-TIME ping-pong indices (ss&1): next chunk's B
// ldmatrix issues right after this chunk's barrier, so this chunk's MMAs run
// from registers loaded LAST chunk. Static indexing avoids the r13 local-mem
// spill; wait->barrier->read order avoids the r12 race.
// Group accounting: prologue commits 3; each iter commits 1 at its end. At
// iter c, 3+c groups committed; cp_wait<1> -> stages <= c+1 complete; the
// barrier then publishes them before the stage-c A read and stage-(c+1) B
// prefetch. Slot (c-1)%4 overwritten at iter end: last readers were iters
// c-1 (A) / c-2 (B-prefetch), both before this iter's barrier.
//   A: [B, M, K] f16 (K contig) -> ldmatrix;  W: [S, K, N] f16 (N contig)
//   -> ldmatrix.trans.
//   A rows 48B stride; B rows 272B stride (68 words, 68 mod 32 = 4) ->
//   conflict-free LDSM phases. Requires K % 64 == 0 (K=512, 1024 ok).
// ---------------------------------------------------------------------------
#define NSTAGE 4
static constexpr int A_ROW_B = 48;
static constexpr int B_ROW_B = 272;
static constexpr int A_STG = 128 * A_ROW_B;       // 6144 B
static constexpr int B_STG = 16 * B_ROW_B;        // 4352 B
static constexpr int STG_B = A_STG + B_STG;       // 10496 B
static constexpr int SMEM_DYN = NSTAGE * STG_B;   // 41984 B

template <bool DO_GELU, bool DO_BIAS, bool STORE_HALF>
__global__ __launch_bounds__(256, 2)
void subject_hgemm(const __half* __restrict__ A_base,
                   const __half* __restrict__ W_base,
                   const int* __restrict__ sid_raw,
                   const float* __restrict__ bias_base,
                   void* __restrict__ C_base,
                   int M, int N, int K)
{
    const int b = blockIdx.z;
    const int s = load_sid(sid_raw, b);
    const __half* A = A_base + (size_t)b * M * K;
    const __half* W = W_base + (size_t)s * K * N;
    const int m0 = blockIdx.y * 128;
    const int n0 = blockIdx.x * 128;

    extern __shared__ char dsm[];
    const uint32_t smem0 = smem_u32(dsm);

    const int tid = threadIdx.x;
    const int wid = tid >> 5;
    const int lane = tid & 31;
    const int wm = wid >> 1;   // 0..3 -> 32-row slab
    const int wn = wid & 1;    // 0..1 -> 64-col slab
    const int g = lane >> 2;   // 0..7
    const int t4 = lane & 3;   // 0..3

    // cp.async A: thread -> m-row tid>>1, 16B half tid&1.
    const int aR = tid >> 1, aH = tid & 1;
    const uint32_t cpOffA = (uint32_t)(aR * A_ROW_B + aH * 16);
    // cp.async B: thread -> k-row tid>>4, 16B segment tid&15 (coalesced in n).
    const int bR = tid >> 4, bS = tid & 15;
    const uint32_t cpOffB = (uint32_t)(A_STG + bR * B_ROW_B + bS * 16);

    // Producer pointers: advance by 16 (A) / 16*N (B) halves per chunk.
    const __half* AgP = A + (size_t)(m0 + aR) * K + aH * 8;
    const __half* BgP = W + (size_t)bR * N + n0 + bS * 8;
    const ptrdiff_t bStep = (ptrdiff_t)16 * N;

    // ldmatrix lane addresses.
    const uint32_t aAddr0 = smem0
        + (uint32_t)((wm * 32 + (lane & 15)) * A_ROW_B + (lane >> 4) * 16);
    const int bRow = ((lane >> 3) & 1) * 8 + (lane & 7);  // k row within 16
    const int bNh = (lane >> 4) * 8;                       // n sub-offset
    const uint32_t bAddr0 = smem0
        + (uint32_t)(A_STG + bRow * B_ROW_B + (wn * 64 + bNh) * 2);

    const int NC = K / 16;   // 32 or 64; divisible by NSTAGE=4

    float acc[2][8][4];
    #pragma unroll
    for (int i = 0; i < 2; i++)
        #pragma unroll
        for (int j = 0; j < 8; j++)
            #pragma unroll
            for (int q = 0; q < 4; q++)
                acc[i][j][q] = 0.0f;

    // Prologue: issue stages 0..2 into slots 0..2.
    #pragma unroll
    for (int c = 0; c < NSTAGE - 1; c++) {
        cp_async16(smem0 + (uint32_t)(c * STG_B) + cpOffA, AgP);
        cp_async16(smem0 + (uint32_t)(c * STG_B) + cpOffB, BgP);
        cp_commit();
        AgP += 16;
        BgP += bStep;
    }

    // Preload chunk-0 B fragments (stage 0, slot 0, buffer 0).
    uint32_t bf[2][4][4];   // ping-pong, ALL indices compile-time
    cp_wait<2>();           // stage 0 complete (own copies)
    __syncthreads();        // publish all threads' stage-0 copies
    #pragma unroll
    for (int j = 0; j < 4; j++)
        ldsm_x4_t(bf[0][j], bAddr0 + (uint32_t)(j * 32));

    #pragma unroll 1
    for (int cc = 0; cc < NC; cc += NSTAGE) {
        #pragma unroll
        for (int ss = 0; ss < NSTAGE; ss++) {
            const int c = cc + ss;

            cp_wait<1>();        // stages <= c+1 complete (own copies)
            __syncthreads();     // publish all threads' copies

            const uint32_t soffC = (uint32_t)(ss * STG_B);  // constant

            // Current A fragments (stage c).
            uint32_t af[2][4];
            ldsm_x4(af[0], aAddr0 + soffC);
            ldsm_x4(af[1], aAddr0 + soffC + 16 * A_ROW_B);

            // Prefetch next chunk's B fragments (stage c+1) into buffer
            // (ss+1)&1 — compile-time index.
            if (c + 1 < NC) {
                const uint32_t soffN =
                    (uint32_t)(((ss + 1) % NSTAGE) * STG_B);  // constant
                #pragma unroll
                for (int j = 0; j < 4; j++)
                    ldsm_x4_t(bf[(ss + 1) & 1][j],
                              bAddr0 + soffN + (uint32_t)(j * 32));
            }

            // MMAs for chunk c: B fragments prefetched last chunk (buffer
            // ss&1, compile-time), A fragments have short LDS exposure only.
            #pragma unroll
            for (int fm = 0; fm < 2; fm++)
                #pragma unroll
                for (int j = 0; j < 4; j++) {
                    mma_f16(acc[fm][2 * j + 0], af[fm],
                            bf[ss & 1][j][0], bf[ss & 1][j][1]);
                    mma_f16(acc[fm][2 * j + 1], af[fm],
                            bf[ss & 1][j][2], bf[ss & 1][j][3]);
                }

            // Refill slot (ss+3)%4 with stage c+3 (constant slot address).
            if (c + NSTAGE - 1 < NC) {
                const uint32_t base =
                    smem0 + (uint32_t)(((ss + NSTAGE - 1) % NSTAGE) * STG_B);
                cp_async16(base + cpOffA, AgP);
                cp_async16(base + cpOffB, BgP);
                AgP += 16;
                BgP += bStep;
            }
            cp_commit();         // uniform group count (empty ok)
        }
    }

    // ---- epilogue ----
    const float* brow = DO_BIAS ? (bias_base + (size_t)s * N + n0) : nullptr;

    #pragma unroll
    for (int fm = 0; fm < 2; fm++) {
        const int r0 = m0 + wm * 32 + fm * 16 + g;
        #pragma unroll
        for (int fn = 0; fn < 8; fn++) {
            const int col = wn * 64 + fn * 8 + t4 * 2;
            #pragma unroll
            for (int h2 = 0; h2 < 2; h2++) {
                const int row = r0 + 8 * h2;
                float v0 = acc[fm][fn][2 * h2 + 0];
                float v1 = acc[fm][fn][2 * h2 + 1];
                if (DO_BIAS) {
                    v0 += brow[col];
                    v1 += brow[col + 1];
                }
                if (DO_GELU) {
                    v0 = 0.5f * v0 * (1.0f + erff(v0 * 0.70710678118654752f));
                    v1 = 0.5f * v1 * (1.0f + erff(v1 * 0.70710678118654752f));
                }
                if (STORE_HALF) {
                    __half2 hv = __floats2half2_rn(v0, v1);
                    *reinterpret_cast<__half2*>(
                        (__half*)C_base + (size_t)b * M * N +
                        (size_t)row * N + n0 + col) = hv;
                } else {
                    *reinterpret_cast<float2*>(
                        (float*)C_base + (size_t)b * M * N +
                        (size_t)row * N + n0 + col) = make_float2(v0, v1);
                }
            }
        }
    }
}

// ---------------------------------------------------------------------------
extern "C" void kernel_launch(void* const* d_in, const int* in_sizes, int n_in,
                              void* d_out, int out_size) {
    const float* x = (const float*)d_in[0];     // [32, 512, 512]
    const int* sid_raw = (const int*)d_in[1];   // [32] int32 or int64 (sniffed)
    const float* w1 = (const float*)d_in[2];    // [64, 512, 1024]
    const float* w2 = (const float*)d_in[3];    // [64, 1024, 512]
    const float* bias = (const float*)d_in[4];  // [64, 512]
    float* out = (float*)d_out;                 // [32, 512, 512]

    const int B = 32, T = 512, D = 512, MID = 1024, O = 512;
    (void)in_sizes; (void)n_in; (void)out_size;

    __half *x16, *h16, *w1h, *w2h;
    cudaGetSymbolAddress((void**)&x16, g_x16);
    cudaGetSymbolAddress((void**)&h16, g_h16);
    cudaGetSymbolAddress((void**)&w1h, g_w1h);
    cudaGetSymbolAddress((void**)&w2h, g_w2h);

    (void)cudaFuncSetAttribute(
        (const void*)subject_hgemm<true, false, true>,
        cudaFuncAttributeMaxDynamicSharedMemorySize, SMEM_DYN);
    (void)cudaFuncSetAttribute(
        (const void*)subject_hgemm<false, true, false>,
        cudaFuncAttributeMaxDynamicSharedMemorySize, SMEM_DYN);

    // 1) x -> f16
    {
        const int n4 = (B * T * D) / 4;
        convert_x_kernel<<<2048, 256>>>((const float4*)x, (uint2*)x16, n4);
    }
    // 2) w1 + w2 -> f16 same layout, used subjects only, one launch
    {
        const int e4 = (D * MID) / 4;
        convert_w_both_kernel<<<dim3(128, 2, 64), 256>>>(
            (const float4*)w1, (uint2*)w1h,
            (const float4*)w2, (uint2*)w2h, sid_raw, e4);
    }
    // 3) GEMM1 + GELU -> h16:  (M=512, N=1024, K=512)
    {
        dim3 grid(MID / 128, T / 128, B);
        subject_hgemm<true, false, true><<<grid, 256, SMEM_DYN>>>(
            x16, w1h, sid_raw, nullptr, (void*)h16, T, MID, D);
    }
    // 4) GEMM2 + bias -> out f32:  (M=512, N=512, K=1024)
    {
        dim3 grid(O / 128, T / 128, B);
        subject_hgemm<false, true, false><<<grid, 256, SMEM_DYN>>>(
            h16, w2h, sid_raw, bias, (void*)out, T, O, MID);
    }
}